// round 2
// baseline (speedup 1.0000x reference)
#include <cuda_runtime.h>

#define LSEQ   2048
#define NBATCH 32
#define TPB    128
#define GSPLIT 8          // GSPLIT*TPB = 1024 query-pairs per batch
#define DTC    0.01f

// log2(e) / sqrt(3): fold softmax scale + natural-exp->exp2 conversion into q
#define QSCALE (1.4426950408889634f / 1.7320508075688772f)

__device__ __forceinline__ float ex2(float x) {
    float r;
    asm("ex2.approx.f32 %0, %1;" : "=f"(r) : "f"(x));
    return r;
}

__global__ void __launch_bounds__(TPB) ac_kernel(
    const float* __restrict__ inputs,
    const float* __restrict__ wi,  const float* __restrict__ bi,
    const float* __restrict__ wo,  const float* __restrict__ bo,
    const float* __restrict__ f1w, const float* __restrict__ f1b,
    const float* __restrict__ f2w, const float* __restrict__ f2b,
    const float* __restrict__ g1w, const float* __restrict__ g1b,
    const float* __restrict__ g2w, const float* __restrict__ g2b,
    const float* __restrict__ m1s, const float* __restrict__ m2s,
    const float* __restrict__ sigma,
    float* __restrict__ out)
{
    extern __shared__ float smem_raw[];
    float4* sk4 = reinterpret_cast<float4*>(smem_raw);           // [LSEQ]: {k0,k1,k2,v0}
    float2* sv2 = reinterpret_cast<float2*>(smem_raw + 4 * LSEQ); // [LSEQ]: {v1,v2}

    const int g = blockIdx.x;
    const int b = blockIdx.y;
    const int t = threadIdx.x;

    const float scl0 = sigma[0] + 1e-5f;
    const float scl1 = sigma[1] + 1e-5f;
    const float inv0 = 1.0f / scl0;
    const float inv1 = 1.0f / scl1;
    const float* __restrict__ xb = inputs + (size_t)b * LSEQ * 3;

    // ---------------- Phase A: build K,V for this batch in smem ----------------
    {
        float wk[9], wv[9], bk[3], bv[3];
        #pragma unroll
        for (int i = 0; i < 9; i++) { wk[i] = wi[9 + i]; wv[i] = wi[18 + i]; }
        #pragma unroll
        for (int i = 0; i < 3; i++) { bk[i] = bi[3 + i]; bv[i] = bi[6 + i]; }

        for (int r = t; r < LSEQ; r += TPB) {
            float x0 = xb[3 * r + 0];
            float x1 = xb[3 * r + 1] * inv0;
            float x2 = xb[3 * r + 2] * inv1;
            float k0 = bk[0] + wk[0] * x0 + wk[1] * x1 + wk[2] * x2;
            float k1 = bk[1] + wk[3] * x0 + wk[4] * x1 + wk[5] * x2;
            float k2 = bk[2] + wk[6] * x0 + wk[7] * x1 + wk[8] * x2;
            float v0 = bv[0] + wv[0] * x0 + wv[1] * x1 + wv[2] * x2;
            float v1 = bv[1] + wv[3] * x0 + wv[4] * x1 + wv[5] * x2;
            float v2 = bv[2] + wv[6] * x0 + wv[7] * x1 + wv[8] * x2;
            sk4[r] = make_float4(k0, k1, k2, v0);
            sv2[r] = make_float2(v1, v2);
        }
    }
    __syncthreads();

    // ---------------- Phase B: adjacent query pair (2m, 2m+1), shared j-loop ----
    const int m  = g * TPB + t;        // pair index 0..1023
    const int ia = 2 * m;
    const int ib = 2 * m + 1;

    float qa0, qa1, qa2, qb0, qb1, qb2;
    {
        float wq[9], bq[3];
        #pragma unroll
        for (int i = 0; i < 9; i++) wq[i] = wi[i];
        #pragma unroll
        for (int i = 0; i < 3; i++) bq[i] = bi[i];

        float xa0 = xb[3 * ia + 0];
        float xa1 = xb[3 * ia + 1] * inv0;
        float xa2 = xb[3 * ia + 2] * inv1;
        qa0 = (bq[0] + wq[0] * xa0 + wq[1] * xa1 + wq[2] * xa2) * QSCALE;
        qa1 = (bq[1] + wq[3] * xa0 + wq[4] * xa1 + wq[5] * xa2) * QSCALE;
        qa2 = (bq[2] + wq[6] * xa0 + wq[7] * xa1 + wq[8] * xa2) * QSCALE;

        float xb0 = xb[3 * ib + 0];
        float xb1 = xb[3 * ib + 1] * inv0;
        float xb2 = xb[3 * ib + 2] * inv1;
        qb0 = (bq[0] + wq[0] * xb0 + wq[1] * xb1 + wq[2] * xb2) * QSCALE;
        qb1 = (bq[1] + wq[3] * xb0 + wq[4] * xb1 + wq[5] * xb2) * QSCALE;
        qb2 = (bq[2] + wq[6] * xb0 + wq[7] * xb1 + wq[8] * xb2) * QSCALE;
    }

    float dena = 0.0f, a0 = 0.0f, a1 = 0.0f, a2 = 0.0f;
    float denb = 0.0f, c0 = 0.0f, c1 = 0.0f, c2 = 0.0f;

    // shared loop: j = 0..2m (both queries); one extra j = 2m+1 for query b
    #pragma unroll 4
    for (int j = 0; j <= ia; j++) {
        float4 kf = sk4[j];
        float2 vf = sv2[j];
        float sa = qa0 * kf.x + qa1 * kf.y + qa2 * kf.z;
        float sb = qb0 * kf.x + qb1 * kf.y + qb2 * kf.z;
        float wa = ex2(sa);
        float wb = ex2(sb);
        dena += wa;  a0 += wa * kf.w;  a1 += wa * vf.x;  a2 += wa * vf.y;
        denb += wb;  c0 += wb * kf.w;  c1 += wb * vf.x;  c2 += wb * vf.y;
    }
    {   // tail: j = ib for query b only
        float4 kf = sk4[ib];
        float2 vf = sv2[ib];
        float sb = qb0 * kf.x + qb1 * kf.y + qb2 * kf.z;
        float wb = ex2(sb);
        denb += wb;  c0 += wb * kf.w;  c1 += wb * vf.x;  c2 += wb * vf.y;
    }

    float ra = 1.0f / dena;
    float rb = 1.0f / denb;
    float ctxa0 = a0 * ra, ctxa1 = a1 * ra, ctxa2 = a2 * ra;
    float ctxb0 = c0 * rb, ctxb1 = c1 * rb, ctxb2 = c2 * rb;

    // -------- epilogue params (loaded post-loop; L1-hot) --------
    float wo10 = wo[3], wo11 = wo[4], wo12 = wo[5];
    float wo20 = wo[6], wo21 = wo[7], wo22 = wo[8];
    float bo1 = bo[1], bo2 = bo[2];
    float G10 = g1w[0], G11 = g1w[1], G12 = g1w[2], G1B = g1b[0];
    float G20 = g2w[0], G21 = g2w[1], G22 = g2w[2], G2B = g2b[0];
    float F10 = f1w[0], F11 = f1w[1], F12 = f1w[2], F1B = f1b[0];
    float F20 = f2w[0], F21 = f2w[1], F22 = f2w[2], F2B = f2b[0];
    float M1 = m1s[0], M2 = m2s[0];

    #pragma unroll
    for (int qq = 0; qq < 2; qq++) {
        float x0 = qq ? ctxb0 : ctxa0;
        float x1 = qq ? ctxb1 : ctxa1;
        float x2 = qq ? ctxb2 : ctxa2;
        int   i  = qq ? ib : ia;

        float s1 = bo1 + wo10 * x0 + wo11 * x1 + wo12 * x2;
        float s2 = bo2 + wo20 * x0 + wo21 * x1 + wo22 * x2;

        float o[8];
        {
            float d1 = (G10 + G11 * s1 + G12 * s2 + G1B) * M1;
            float d2 = (G20 + G21 * s1 + G22 * s2 + G2B) * M2;
            s1 += DTC * d1; s2 += DTC * d2;
            o[0] = s1 * scl0; o[1] = s2 * scl1;
        }
        {
            float d1 = (G10 + G11 * s1 + G12 * s2 + G1B) * M1;
            float d2 = (G20 + G21 * s1 + G22 * s2 + G2B) * M2;
            s1 += DTC * d1; s2 += DTC * d2;
            o[2] = s1 * scl0; o[3] = s2 * scl1;
        }
        {
            float d1 = (G10 + G11 * s1 + G12 * s2 + G1B) * M1;
            float d2 = (G20 + G21 * s1 + G22 * s2 + G2B) * M2;
            s1 += DTC * d1; s2 += DTC * d2;
            o[4] = s1 * scl0; o[5] = s2 * scl1;
        }
        {
            float v1 = (F10 + F11 * s1 + F12 * s2 + F1B) * M1;
            float v2 = (F20 + F21 * s1 + F22 * s2 + F2B) * M2;
            o[6] = (s1 + v1 * DTC) * scl0;
            o[7] = (s2 + v2 * DTC) * scl1;
        }

        float4* op = reinterpret_cast<float4*>(out) + ((size_t)(b * LSEQ + i)) * 2;
        op[0] = make_float4(o[0], o[1], o[2], o[3]);
        op[1] = make_float4(o[4], o[5], o[6], o[7]);
    }
}

extern "C" void kernel_launch(void* const* d_in, const int* in_sizes, int n_in,
                              void* d_out, int out_size)
{
    const float* inputs = (const float*)d_in[1];
    const float* wi     = (const float*)d_in[2];
    const float* bi     = (const float*)d_in[3];
    const float* wo     = (const float*)d_in[4];
    const float* bo     = (const float*)d_in[5];
    const float* f1w    = (const float*)d_in[6];
    const float* f1b    = (const float*)d_in[7];
    const float* f2w    = (const float*)d_in[8];
    const float* f2b    = (const float*)d_in[9];
    const float* g1w    = (const float*)d_in[10];
    const float* g1b    = (const float*)d_in[11];
    const float* g2w    = (const float*)d_in[12];
    const float* g2b    = (const float*)d_in[13];
    const float* m1s    = (const float*)d_in[14];
    const float* m2s    = (const float*)d_in[15];
    const float* sigma  = (const float*)d_in[16];
    float* out = (float*)d_out;

    const int smem = LSEQ * (16 + 8);   // 48 KB: float4 K + float2 V
    cudaFuncSetAttribute(ac_kernel, cudaFuncAttributeMaxDynamicSharedMemorySize, smem);

    dim3 grid(GSPLIT, NBATCH);
    ac_kernel<<<grid, TPB, smem>>>(inputs, wi, bi, wo, bo,
                                   f1w, f1b, f2w, f2b,
                                   g1w, g1b, g2w, g2b,
                                   m1s, m2s, sigma, out);
}

// round 3
// speedup vs baseline: 1.9246x; 1.9246x over previous
#include <cuda_runtime.h>

#define LSEQ   2048
#define NBATCH 32
#define TPB    128
#define PAIRS_PER_BLOCK 64        // TPB/2 (2 threads per query-pair)
#define GSPLIT 16                 // blocks per batch = 1024 pairs / 64
#define DTC    0.01f

// log2(e)/sqrt(3): fold softmax scale + e^x -> 2^x conversion into q
#define QSCALE (1.4426950408889634f / 1.7320508075688772f)

__device__ __forceinline__ float ex2(float x) {
    float r;
    asm("ex2.approx.f32 %0, %1;" : "=f"(r) : "f"(x));
    return r;
}

#define PACK2(d, lo, hi)  asm("mov.b64 %0, {%1, %2};" : "=l"(d) : "f"(lo), "f"(hi))
#define UNPACK2(lo, hi, d) asm("mov.b64 {%0, %1}, %2;" : "=f"(lo), "=f"(hi) : "l"(d))
#define FMA2(d, a, b, c)  asm("fma.rn.f32x2 %0, %1, %2, %3;" : "=l"(d) : "l"(a), "l"(b), "l"(c))
#define ADD2(d, a, b)     asm("add.rn.f32x2 %0, %1, %2;" : "=l"(d) : "l"(a), "l"(b))
#define MUL2(d, a, b)     asm("mul.rn.f32x2 %0, %1, %2;" : "=l"(d) : "l"(a), "l"(b))

// Accumulate softmax partials for one query over this thread's parity-subset
// of keys. base points at this parity's duo array; N = number of valid keys
// in the subset (keys are n = 0..N-1; duo m covers n=2m,2m+1).
// Duo layout (float4 x3): A={k0_lo,k0_hi,k1_lo,k1_hi} B={k2_lo,k2_hi,v0_lo,v0_hi}
//                         C={v1_lo,v1_hi,v2_lo,v2_hi}
__device__ __forceinline__ void accum_query(
    const float4* __restrict__ base, int N,
    float q0, float q1, float q2,
    float& den, float& a0, float& a1, float& a2)
{
    unsigned long long q0p, q1p, q2p;
    unsigned long long denp = 0ull, a0p = 0ull, a1p = 0ull, a2p = 0ull;
    PACK2(q0p, q0, q0);
    PACK2(q1p, q1, q1);
    PACK2(q2p, q2, q2);

    const int M = N >> 1;
    #pragma unroll 4
    for (int m = 0; m < M; m++) {
        float4 A = base[3 * m + 0];
        float4 B = base[3 * m + 1];
        float4 C = base[3 * m + 2];
        unsigned long long k0p, k1p, k2p, v0p, v1p, v2p, sp, wp;
        PACK2(k0p, A.x, A.y);
        PACK2(k1p, A.z, A.w);
        PACK2(k2p, B.x, B.y);
        PACK2(v0p, B.z, B.w);
        PACK2(v1p, C.x, C.y);
        PACK2(v2p, C.z, C.w);
        MUL2(sp, q0p, k0p);
        FMA2(sp, q1p, k1p, sp);
        FMA2(sp, q2p, k2p, sp);
        float sx, sy;
        UNPACK2(sx, sy, sp);
        float wx = ex2(sx);
        float wy = ex2(sy);
        PACK2(wp, wx, wy);
        ADD2(denp, denp, wp);
        FMA2(a0p, wp, v0p, a0p);
        FMA2(a1p, wp, v1p, a1p);
        FMA2(a2p, wp, v2p, a2p);
    }
    float dl, dh, xl, xh, yl, yh, zl, zh;
    UNPACK2(dl, dh, denp);
    UNPACK2(xl, xh, a0p);
    UNPACK2(yl, yh, a1p);
    UNPACK2(zl, zh, a2p);
    den = dl + dh; a0 = xl + xh; a1 = yl + yh; a2 = zl + zh;

    if (N & 1) {   // tail: lone key = lo slot of duo M
        float4 A = base[3 * M + 0];
        float4 B = base[3 * M + 1];
        float4 C = base[3 * M + 2];
        float s = q0 * A.x + q1 * A.z + q2 * B.x;
        float w = ex2(s);
        den += w; a0 += w * B.z; a1 += w * C.x; a2 += w * C.z;
    }
}

__global__ void __launch_bounds__(TPB) ac_kernel(
    const float* __restrict__ inputs,
    const float* __restrict__ wi,  const float* __restrict__ bi,
    const float* __restrict__ wo,  const float* __restrict__ bo,
    const float* __restrict__ f1w, const float* __restrict__ f1b,
    const float* __restrict__ f2w, const float* __restrict__ f2b,
    const float* __restrict__ g1w, const float* __restrict__ g1b,
    const float* __restrict__ g2w, const float* __restrict__ g2b,
    const float* __restrict__ m1s, const float* __restrict__ m2s,
    const float* __restrict__ sigma,
    float* __restrict__ out)
{
    // Per parity h: 512 duos x 3 float4 = 1536 float4. Total 48 KB.
    extern __shared__ float4 sk[];

    const int g = blockIdx.x;
    const int b = blockIdx.y;
    const int t = threadIdx.x;

    const float scl0 = sigma[0] + 1e-5f;
    const float scl1 = sigma[1] + 1e-5f;
    const float inv0 = 1.0f / scl0;
    const float inv1 = 1.0f / scl1;
    const float* __restrict__ xb = inputs + (size_t)b * LSEQ * 3;

    // ---------------- Phase A: build K,V into parity-duo layout ----------------
    {
        float wk[9], wv[9], bk[3], bv[3];
        #pragma unroll
        for (int i = 0; i < 9; i++) { wk[i] = wi[9 + i]; wv[i] = wi[18 + i]; }
        #pragma unroll
        for (int i = 0; i < 3; i++) { bk[i] = bi[3 + i]; bv[i] = bi[6 + i]; }

        for (int r = t; r < LSEQ; r += TPB) {
            float x0 = xb[3 * r + 0];
            float x1 = xb[3 * r + 1] * inv0;
            float x2 = xb[3 * r + 2] * inv1;
            float k0 = bk[0] + wk[0] * x0 + wk[1] * x1 + wk[2] * x2;
            float k1 = bk[1] + wk[3] * x0 + wk[4] * x1 + wk[5] * x2;
            float k2 = bk[2] + wk[6] * x0 + wk[7] * x1 + wk[8] * x2;
            float v0 = bv[0] + wv[0] * x0 + wv[1] * x1 + wv[2] * x2;
            float v1 = bv[1] + wv[3] * x0 + wv[4] * x1 + wv[5] * x2;
            float v2 = bv[2] + wv[6] * x0 + wv[7] * x1 + wv[8] * x2;

            int h = r & 1, n = r >> 1, m = n >> 1, slot = n & 1;
            float* dst = reinterpret_cast<float*>(sk + (size_t)h * 1536 + 3 * m);
            dst[0 + slot]  = k0;
            dst[2 + slot]  = k1;
            dst[4 + slot]  = k2;
            dst[6 + slot]  = v0;
            dst[8 + slot]  = v1;
            dst[10 + slot] = v2;
        }
    }
    __syncthreads();

    // ---------------- Phase B: pair (p, 2047-p), 2 threads per pair ----------------
    const int h  = t & 1;                       // key-parity this thread covers
    const int p  = g * PAIRS_PER_BLOCK + (t >> 1);
    const int ia = p;
    const int ib = LSEQ - 1 - p;

    float qa0, qa1, qa2, qb0, qb1, qb2;
    {
        float wq[9], bq[3];
        #pragma unroll
        for (int i = 0; i < 9; i++) wq[i] = wi[i];
        #pragma unroll
        for (int i = 0; i < 3; i++) bq[i] = bi[i];

        float x0 = xb[3 * ia + 0];
        float x1 = xb[3 * ia + 1] * inv0;
        float x2 = xb[3 * ia + 2] * inv1;
        qa0 = (bq[0] + wq[0] * x0 + wq[1] * x1 + wq[2] * x2) * QSCALE;
        qa1 = (bq[1] + wq[3] * x0 + wq[4] * x1 + wq[5] * x2) * QSCALE;
        qa2 = (bq[2] + wq[6] * x0 + wq[7] * x1 + wq[8] * x2) * QSCALE;

        float y0 = xb[3 * ib + 0];
        float y1 = xb[3 * ib + 1] * inv0;
        float y2 = xb[3 * ib + 2] * inv1;
        qb0 = (bq[0] + wq[0] * y0 + wq[1] * y1 + wq[2] * y2) * QSCALE;
        qb1 = (bq[1] + wq[3] * y0 + wq[4] * y1 + wq[5] * y2) * QSCALE;
        qb2 = (bq[2] + wq[6] * y0 + wq[7] * y1 + wq[8] * y2) * QSCALE;
    }

    const float4* base = sk + (size_t)h * 1536;
    const int Na = (p >= h) ? (((p  - h) >> 1) + 1) : 0;   // keys j<=ia, j==h (mod 2)
    const int Nb = ((ib - h) >> 1) + 1;                    // keys j<=ib, j==h (mod 2)

    float dena, a0, a1, a2, denb, c0, c1, c2;
    accum_query(base, Na, qa0, qa1, qa2, dena, a0, a1, a2);
    accum_query(base, Nb, qb0, qb1, qb2, denb, c0, c1, c2);

    // combine the two parity partials (lanes 2k / 2k+1 hold the same pair)
    const unsigned full = 0xffffffffu;
    dena += __shfl_xor_sync(full, dena, 1);
    a0   += __shfl_xor_sync(full, a0,   1);
    a1   += __shfl_xor_sync(full, a1,   1);
    a2   += __shfl_xor_sync(full, a2,   1);
    denb += __shfl_xor_sync(full, denb, 1);
    c0   += __shfl_xor_sync(full, c0,   1);
    c1   += __shfl_xor_sync(full, c1,   1);
    c2   += __shfl_xor_sync(full, c2,   1);

    // lane h=0 finishes query a, lane h=1 finishes query b
    const float den = h ? denb : dena;
    const float r   = 1.0f / den;
    const float x0  = (h ? c0 : a0) * r;
    const float x1  = (h ? c1 : a1) * r;
    const float x2  = (h ? c2 : a2) * r;
    const int   i   = h ? ib : ia;

    // -------- epilogue (L1-hot scalar params) --------
    float wo10 = wo[3], wo11 = wo[4], wo12 = wo[5];
    float wo20 = wo[6], wo21 = wo[7], wo22 = wo[8];
    float bo1 = bo[1], bo2 = bo[2];
    float G10 = g1w[0], G11 = g1w[1], G12 = g1w[2], G1B = g1b[0];
    float G20 = g2w[0], G21 = g2w[1], G22 = g2w[2], G2B = g2b[0];
    float F10 = f1w[0], F11 = f1w[1], F12 = f1w[2], F1B = f1b[0];
    float F20 = f2w[0], F21 = f2w[1], F22 = f2w[2], F2B = f2b[0];
    float M1 = m1s[0], M2 = m2s[0];

    float s1 = bo1 + wo10 * x0 + wo11 * x1 + wo12 * x2;
    float s2 = bo2 + wo20 * x0 + wo21 * x1 + wo22 * x2;

    float o[8];
    {
        float d1 = (G10 + G11 * s1 + G12 * s2 + G1B) * M1;
        float d2 = (G20 + G21 * s1 + G22 * s2 + G2B) * M2;
        s1 += DTC * d1; s2 += DTC * d2;
        o[0] = s1 * scl0; o[1] = s2 * scl1;
    }
    {
        float d1 = (G10 + G11 * s1 + G12 * s2 + G1B) * M1;
        float d2 = (G20 + G21 * s1 + G22 * s2 + G2B) * M2;
        s1 += DTC * d1; s2 += DTC * d2;
        o[2] = s1 * scl0; o[3] = s2 * scl1;
    }
    {
        float d1 = (G10 + G11 * s1 + G12 * s2 + G1B) * M1;
        float d2 = (G20 + G21 * s1 + G22 * s2 + G2B) * M2;
        s1 += DTC * d1; s2 += DTC * d2;
        o[4] = s1 * scl0; o[5] = s2 * scl1;
    }
    {
        float v1 = (F10 + F11 * s1 + F12 * s2 + F1B) * M1;
        float v2 = (F20 + F21 * s1 + F22 * s2 + F2B) * M2;
        o[6] = (s1 + v1 * DTC) * scl0;
        o[7] = (s2 + v2 * DTC) * scl1;
    }

    float4* op = reinterpret_cast<float4*>(out) + ((size_t)(b * LSEQ + i)) * 2;
    op[0] = make_float4(o[0], o[1], o[2], o[3]);
    op[1] = make_float4(o[4], o[5], o[6], o[7]);
}

extern "C" void kernel_launch(void* const* d_in, const int* in_sizes, int n_in,
                              void* d_out, int out_size)
{
    const float* inputs = (const float*)d_in[1];
    const float* wi     = (const float*)d_in[2];
    const float* bi     = (const float*)d_in[3];
    const float* wo     = (const float*)d_in[4];
    const float* bo     = (const float*)d_in[5];
    const float* f1w    = (const float*)d_in[6];
    const float* f1b    = (const float*)d_in[7];
    const float* f2w    = (const float*)d_in[8];
    const float* f2b    = (const float*)d_in[9];
    const float* g1w    = (const float*)d_in[10];
    const float* g1b    = (const float*)d_in[11];
    const float* g2w    = (const float*)d_in[12];
    const float* g2b    = (const float*)d_in[13];
    const float* m1s    = (const float*)d_in[14];
    const float* m2s    = (const float*)d_in[15];
    const float* sigma  = (const float*)d_in[16];
    float* out = (float*)d_out;

    const int smem = 2 * 1536 * (int)sizeof(float4);   // 48 KB
    cudaFuncSetAttribute(ac_kernel, cudaFuncAttributeMaxDynamicSharedMemorySize, smem);

    dim3 grid(GSPLIT, NBATCH);   // 512 blocks: single wave at 4 blocks/SM (smem-limited)
    ac_kernel<<<grid, TPB, smem>>>(inputs, wi, bi, wo, bo,
                                   f1w, f1b, f2w, f2b,
                                   g1w, g1b, g2w, g2b,
                                   m1s, m2s, sigma, out);
}